// round 12
// baseline (speedup 1.0000x reference)
#include <cuda_runtime.h>
#include <cstddef>
#include <cstdint>

#define N_NODES 100000
#define N_EDGES 1600000
#define NB_SCAN 391            // ceil(100000 / 256)

// ---------------- scratch (static device arrays; no cudaMalloc) ------------
__device__ float g_t1[(size_t)N_NODES * 128];     // x @ W_neigh1
__device__ float g_hself1[(size_t)N_NODES * 128]; // x @ W_self1 + b1
__device__ float g_t2[(size_t)N_NODES * 64];      // h1_relu @ W_neigh2
__device__ float g_hself2[(size_t)N_NODES * 64];  // h1_relu @ W_self2 + b2
__device__ int   g_deg[N_NODES];                  // zero-init; re-zeroed by scatter
__device__ int   g_off[N_NODES + 1];
__device__ int   g_cur[N_NODES];
__device__ int   g_ssrc[N_EDGES];
__device__ int   g_bsum[512];                     // per-block degree sums
__device__ int   g_bpref[512];                    // exclusive prefix of block sums

// ---------------- CSR build (parallel two-level scan) -----------------------
__global__ void count_deg_kernel(const int* __restrict__ dst) {
    int e = blockIdx.x * blockDim.x + threadIdx.x;
    if (e < N_EDGES) atomicAdd(&g_deg[dst[e]], 1);
}

__global__ __launch_bounds__(256)
void block_sum_kernel() {
    __shared__ int sh[8];
    int i = blockIdx.x * 256 + threadIdx.x;
    int v = (i < N_NODES) ? g_deg[i] : 0;
    for (int o = 16; o > 0; o >>= 1) v += __shfl_down_sync(0xffffffffu, v, o);
    if ((threadIdx.x & 31) == 0) sh[threadIdx.x >> 5] = v;
    __syncthreads();
    if (threadIdx.x < 8) {
        int s = sh[threadIdx.x];
        for (int o = 4; o > 0; o >>= 1) s += __shfl_down_sync(0xffu, s, o);
        if (threadIdx.x == 0) g_bsum[blockIdx.x] = s;
    }
}

__global__ __launch_bounds__(512)
void block_scan_kernel() {
    __shared__ int sh[512];
    int t = threadIdx.x;
    int v = (t < NB_SCAN) ? g_bsum[t] : 0;
    sh[t] = v;
    __syncthreads();
    for (int o = 1; o < 512; o <<= 1) {
        int u = (t >= o) ? sh[t - o] : 0;
        __syncthreads();
        sh[t] += u;
        __syncthreads();
    }
    if (t < NB_SCAN) g_bpref[t] = sh[t] - v;   // exclusive
}

__global__ __launch_bounds__(256)
void scatter_offsets_kernel() {
    __shared__ int sh[256];
    int t = threadIdx.x;
    int i = blockIdx.x * 256 + t;
    int v = (i < N_NODES) ? g_deg[i] : 0;
    sh[t] = v;
    __syncthreads();
    for (int o = 1; o < 256; o <<= 1) {
        int u = (t >= o) ? sh[t - o] : 0;
        __syncthreads();
        sh[t] += u;
        __syncthreads();
    }
    if (i < N_NODES) {
        int off = g_bpref[blockIdx.x] + sh[t] - v;
        g_off[i] = off;
        g_cur[i] = off;
        g_deg[i] = 0;                               // reset for next run
    }
    if (blockIdx.x == 0 && t == 0) g_off[N_NODES] = N_EDGES;
}

__global__ void fill_csr_kernel(const int* __restrict__ src,
                                const int* __restrict__ dst) {
    int e = blockIdx.x * blockDim.x + threadIdx.x;
    if (e < N_EDGES) {
        int p = atomicAdd(&g_cur[dst[e]], 1);
        g_ssrc[p] = src[e];
    }
}

// ---------------- 3xTF32 tensor-core dual-output GEMM (pipelined) ----------
__device__ __forceinline__ float tf32_rn(float v) {
    uint32_t o;
    asm("cvt.rna.tf32.f32 %0, %1;" : "=r"(o) : "f"(v));
    return __uint_as_float(o);
}

__device__ __forceinline__ void mma_tf32(float* c,
                                         uint32_t a0, uint32_t a1, uint32_t a2, uint32_t a3,
                                         uint32_t b0, uint32_t b1) {
    asm volatile(
        "mma.sync.aligned.m16n8k8.row.col.f32.tf32.tf32.f32 "
        "{%0,%1,%2,%3}, {%4,%5,%6,%7}, {%8,%9}, {%0,%1,%2,%3};\n"
        : "+f"(c[0]), "+f"(c[1]), "+f"(c[2]), "+f"(c[3])
        : "r"(a0), "r"(a1), "r"(a2), "r"(a3), "r"(b0), "r"(b1));
}

__global__ __launch_bounds__(256, 2)
void tf32_dual_gemm(const float* __restrict__ A,
                    const float* __restrict__ B0,
                    const float* __restrict__ B1,
                    const float* __restrict__ bias,
                    float* __restrict__ out0,
                    float* __restrict__ out1,
                    int M, int n0) {
    constexpr int BM = 128, BN = 128, BK = 16, K = 128;
    __shared__ float2 As2[BK][BM + 2];
    __shared__ float2 Bs2[BK][BN + 2];

    const int tid  = threadIdx.x;
    const int lane = tid & 31;
    const int warp = tid >> 5;
    const int g    = lane >> 2;
    const int tg   = lane & 3;
    const int warpM = (warp >> 1) * 32;
    const int warpN = (warp & 1) * 64;
    const int brow = blockIdx.x * BM;
    const int bcol = blockIdx.y * BN;

    const int aRow = tid >> 1;
    const int aCol = (tid & 1) * 8;
    const bool aOK = (brow + aRow) < M;
    const float* aBase = A + (size_t)(brow + aRow) * K + aCol;

    const int bK = tid >> 4;
    const int bC = (tid & 15) * 8;
    const int bGC = bcol + bC;
    const float* bHalf = (bGC < n0) ? B0 : B1;
    const int   bCol   = (bGC < n0) ? bGC : (bGC - n0);

    float acc[2][8][4];
#pragma unroll
    for (int mt = 0; mt < 2; mt++)
#pragma unroll
        for (int nt = 0; nt < 8; nt++)
#pragma unroll
            for (int q = 0; q < 4; q++) acc[mt][nt][q] = 0.f;

    // ---- prologue: load tile 0 into registers, stage to smem ----
    float4 ra0 = make_float4(0.f, 0.f, 0.f, 0.f), ra1 = ra0;
    if (aOK) {
        ra0 = *reinterpret_cast<const float4*>(aBase);
        ra1 = *reinterpret_cast<const float4*>(aBase + 4);
    }
    float4 rb0 = *reinterpret_cast<const float4*>(bHalf + (size_t)bK * n0 + bCol);
    float4 rb1 = *reinterpret_cast<const float4*>(bHalf + (size_t)bK * n0 + bCol + 4);

    {
        float av[8] = {ra0.x, ra0.y, ra0.z, ra0.w, ra1.x, ra1.y, ra1.z, ra1.w};
        float bv[8] = {rb0.x, rb0.y, rb0.z, rb0.w, rb1.x, rb1.y, rb1.z, rb1.w};
#pragma unroll
        for (int j = 0; j < 8; j++) {
            float hi = tf32_rn(av[j]);
            As2[aCol + j][aRow] = make_float2(hi, tf32_rn(av[j] - hi));
            float bh = tf32_rn(bv[j]);
            Bs2[bK][bC + j] = make_float2(bh, tf32_rn(bv[j] - bh));
        }
    }
    __syncthreads();

    for (int k0 = 0; k0 < K; k0 += BK) {
        const int kn = k0 + BK;
        const bool more = kn < K;
        // ---- prefetch next tile into registers (overlaps with compute) ----
        if (more) {
            if (aOK) {
                ra0 = *reinterpret_cast<const float4*>(aBase + kn);
                ra1 = *reinterpret_cast<const float4*>(aBase + kn + 4);
            }
            rb0 = *reinterpret_cast<const float4*>(bHalf + (size_t)(kn + bK) * n0 + bCol);
            rb1 = *reinterpret_cast<const float4*>(bHalf + (size_t)(kn + bK) * n0 + bCol + 4);
        }

        // ---- compute current tile ----
#pragma unroll
        for (int kk = 0; kk < BK; kk += 8) {
            float2 af[2][4];
#pragma unroll
            for (int mt = 0; mt < 2; mt++) {
                int m = warpM + mt * 16 + g;
                af[mt][0] = As2[kk + tg][m];
                af[mt][1] = As2[kk + tg][m + 8];
                af[mt][2] = As2[kk + tg + 4][m];
                af[mt][3] = As2[kk + tg + 4][m + 8];
            }
#pragma unroll
            for (int nt = 0; nt < 8; nt++) {
                int n = warpN + nt * 8 + g;
                float2 bf0 = Bs2[kk + tg][n];
                float2 bf1 = Bs2[kk + tg + 4][n];
                uint32_t bh0 = __float_as_uint(bf0.x), bl0 = __float_as_uint(bf0.y);
                uint32_t bh1 = __float_as_uint(bf1.x), bl1 = __float_as_uint(bf1.y);
#pragma unroll
                for (int mt = 0; mt < 2; mt++) {
                    uint32_t ah0 = __float_as_uint(af[mt][0].x);
                    uint32_t ah1 = __float_as_uint(af[mt][1].x);
                    uint32_t ah2 = __float_as_uint(af[mt][2].x);
                    uint32_t ah3 = __float_as_uint(af[mt][3].x);
                    uint32_t al0 = __float_as_uint(af[mt][0].y);
                    uint32_t al1 = __float_as_uint(af[mt][1].y);
                    uint32_t al2 = __float_as_uint(af[mt][2].y);
                    uint32_t al3 = __float_as_uint(af[mt][3].y);
                    mma_tf32(acc[mt][nt], ah0, ah1, ah2, ah3, bh0, bh1);
                    mma_tf32(acc[mt][nt], ah0, ah1, ah2, ah3, bl0, bl1);
                    mma_tf32(acc[mt][nt], al0, al1, al2, al3, bh0, bh1);
                }
            }
        }

        // ---- stage prefetched tile to smem ----
        if (more) {
            __syncthreads();   // all warps done reading current smem tile
            float av[8] = {ra0.x, ra0.y, ra0.z, ra0.w, ra1.x, ra1.y, ra1.z, ra1.w};
            float bv[8] = {rb0.x, rb0.y, rb0.z, rb0.w, rb1.x, rb1.y, rb1.z, rb1.w};
#pragma unroll
            for (int j = 0; j < 8; j++) {
                float hi = tf32_rn(av[j]);
                As2[aCol + j][aRow] = make_float2(hi, tf32_rn(av[j] - hi));
                float bh = tf32_rn(bv[j]);
                Bs2[bK][bC + j] = make_float2(bh, tf32_rn(bv[j] - bh));
            }
            __syncthreads();
        }
    }

#pragma unroll
    for (int mt = 0; mt < 2; mt++) {
#pragma unroll
        for (int nt = 0; nt < 8; nt++) {
            int gcol = bcol + warpN + nt * 8 + 2 * tg;
            int r0 = brow + warpM + mt * 16 + g;
            int r1 = r0 + 8;
            if (gcol < n0) {
                float bb0 = bias ? bias[gcol] : 0.f;
                float bb1 = bias ? bias[gcol + 1] : 0.f;
                if (r0 < M)
                    *reinterpret_cast<float2*>(out0 + (size_t)r0 * n0 + gcol) =
                        make_float2(acc[mt][nt][0] + bb0, acc[mt][nt][1] + bb1);
                if (r1 < M)
                    *reinterpret_cast<float2*>(out0 + (size_t)r1 * n0 + gcol) =
                        make_float2(acc[mt][nt][2] + bb0, acc[mt][nt][3] + bb1);
            } else {
                int cc = gcol - n0;
                if (r0 < M)
                    *reinterpret_cast<float2*>(out1 + (size_t)r0 * n0 + cc) =
                        make_float2(acc[mt][nt][0], acc[mt][nt][1]);
                if (r1 < M)
                    *reinterpret_cast<float2*>(out1 + (size_t)r1 * n0 + cc) =
                        make_float2(acc[mt][nt][2], acc[mt][nt][3]);
            }
        }
    }
}

// ---------------- layer-1 gather+combine: warp per dst node (D=128) --------
__global__ __launch_bounds__(256)
void gather_combine1(const float* __restrict__ hself,
                     const float* __restrict__ t,
                     float* __restrict__ out_h1,
                     float* __restrict__ out_h1r) {
    int warp = (blockIdx.x * blockDim.x + threadIdx.x) >> 5;
    int lane = threadIdx.x & 31;
    if (warp >= N_NODES) return;
    const int n   = warp;
    const int beg = g_off[n];
    const int end = g_off[n + 1];
    const int lo4 = lane * 4;

    float4 acc = make_float4(0.f, 0.f, 0.f, 0.f);
    int e = beg;
    for (; e + 3 < end; e += 4) {
        int s0 = g_ssrc[e];
        int s1 = g_ssrc[e + 1];
        int s2 = g_ssrc[e + 2];
        int s3 = g_ssrc[e + 3];
        float4 v0 = *reinterpret_cast<const float4*>(t + (size_t)s0 * 128 + lo4);
        float4 v1 = *reinterpret_cast<const float4*>(t + (size_t)s1 * 128 + lo4);
        float4 v2 = *reinterpret_cast<const float4*>(t + (size_t)s2 * 128 + lo4);
        float4 v3 = *reinterpret_cast<const float4*>(t + (size_t)s3 * 128 + lo4);
        acc.x += (v0.x + v1.x) + (v2.x + v3.x);
        acc.y += (v0.y + v1.y) + (v2.y + v3.y);
        acc.z += (v0.z + v1.z) + (v2.z + v3.z);
        acc.w += (v0.w + v1.w) + (v2.w + v3.w);
    }
    for (; e < end; e++) {
        int s0 = g_ssrc[e];
        float4 v0 = *reinterpret_cast<const float4*>(t + (size_t)s0 * 128 + lo4);
        acc.x += v0.x; acc.y += v0.y; acc.z += v0.z; acc.w += v0.w;
    }
    float inv = 1.0f / fmaxf((float)(end - beg), 1.0f);
    float4 hs = *reinterpret_cast<const float4*>(hself + (size_t)n * 128 + lo4);
    float4 h1;
    h1.x = hs.x + acc.x * inv;
    h1.y = hs.y + acc.y * inv;
    h1.z = hs.z + acc.z * inv;
    h1.w = hs.w + acc.w * inv;
    *reinterpret_cast<float4*>(out_h1 + (size_t)n * 128 + lo4) = h1;
    float4 r;
    r.x = fmaxf(h1.x, 0.f); r.y = fmaxf(h1.y, 0.f);
    r.z = fmaxf(h1.z, 0.f); r.w = fmaxf(h1.w, 0.f);
    *reinterpret_cast<float4*>(out_h1r + (size_t)n * 128 + lo4) = r;
}

// ---------------- layer-2 gather+combine: warp per dst node (D=64) ---------
__global__ __launch_bounds__(256)
void gather_combine2(const float* __restrict__ hself,
                     const float* __restrict__ t,
                     float* __restrict__ out_a,
                     float* __restrict__ out_b) {
    int warp = (blockIdx.x * blockDim.x + threadIdx.x) >> 5;
    int lane = threadIdx.x & 31;
    if (warp >= N_NODES) return;
    const int n   = warp;
    const int beg = g_off[n];
    const int end = g_off[n + 1];
    const int lo2 = lane * 2;

    float2 acc = make_float2(0.f, 0.f);
    int e = beg;
    for (; e + 3 < end; e += 4) {
        int s0 = g_ssrc[e];
        int s1 = g_ssrc[e + 1];
        int s2 = g_ssrc[e + 2];
        int s3 = g_ssrc[e + 3];
        float2 v0 = *reinterpret_cast<const float2*>(t + (size_t)s0 * 64 + lo2);
        float2 v1 = *reinterpret_cast<const float2*>(t + (size_t)s1 * 64 + lo2);
        float2 v2 = *reinterpret_cast<const float2*>(t + (size_t)s2 * 64 + lo2);
        float2 v3 = *reinterpret_cast<const float2*>(t + (size_t)s3 * 64 + lo2);
        acc.x += (v0.x + v1.x) + (v2.x + v3.x);
        acc.y += (v0.y + v1.y) + (v2.y + v3.y);
    }
    for (; e < end; e++) {
        int s0 = g_ssrc[e];
        float2 v0 = *reinterpret_cast<const float2*>(t + (size_t)s0 * 64 + lo2);
        acc.x += v0.x; acc.y += v0.y;
    }
    float inv = 1.0f / fmaxf((float)(end - beg), 1.0f);
    float2 hs = *reinterpret_cast<const float2*>(hself + (size_t)n * 64 + lo2);
    float2 h2 = make_float2(hs.x + acc.x * inv, hs.y + acc.y * inv);
    *reinterpret_cast<float2*>(out_a + (size_t)n * 64 + lo2) = h2;
    *reinterpret_cast<float2*>(out_b + (size_t)n * 64 + lo2) = h2;
}

// ---------------- launch ---------------------------------------------------
extern "C" void kernel_launch(void* const* d_in, const int* in_sizes, int n_in,
                              void* d_out, int out_size) {
    const float* x        = (const float*)d_in[0];
    const float* W_self1  = (const float*)d_in[1];
    const float* W_neigh1 = (const float*)d_in[2];
    const float* b1       = (const float*)d_in[3];
    const float* W_self2  = (const float*)d_in[4];
    const float* W_neigh2 = (const float*)d_in[5];
    const float* b2       = (const float*)d_in[6];
    const int*   src      = (const int*)d_in[7];
    const int*   dst      = (const int*)d_in[8];

    float* out = (float*)d_out;
    float* out_h2a = out;                                      // 100000*64
    float* out_h1  = out + (size_t)N_NODES * 64;               // 100000*128
    float* out_h1r = out + (size_t)N_NODES * (64 + 128);       // 100000*128
    float* out_h2b = out + (size_t)N_NODES * (64 + 128 + 128); // 100000*64

    float* t1 = nullptr, *hs1 = nullptr, *t2 = nullptr, *hs2 = nullptr;
    cudaGetSymbolAddress((void**)&t1,  g_t1);
    cudaGetSymbolAddress((void**)&hs1, g_hself1);
    cudaGetSymbolAddress((void**)&t2,  g_t2);
    cudaGetSymbolAddress((void**)&hs2, g_hself2);

    // launches 0..2: CSR count + scan levels
    count_deg_kernel<<<(N_EDGES + 255) / 256, 256>>>(dst);
    block_sum_kernel<<<NB_SCAN, 256>>>();
    block_scan_kernel<<<1, 512>>>();

    // launch 3 (ncu capture slot): layer-1 GEMM (independent of CSR)
    dim3 g1((N_NODES + 127) / 128, 2);
    tf32_dual_gemm<<<g1, 256>>>(x, W_self1, W_neigh1, b1, hs1, t1, N_NODES, 128);

    // launches 4..5: finish CSR
    scatter_offsets_kernel<<<NB_SCAN, 256>>>();
    fill_csr_kernel<<<(N_EDGES + 255) / 256, 256>>>(src, dst);

    // launch 6: layer-1 gather + combine + relu
    int gblocks = (N_NODES * 32 + 255) / 256;  // one warp per node
    gather_combine1<<<gblocks, 256>>>(hs1, t1, out_h1, out_h1r);

    // launch 7: layer-2 GEMM on h1_relu
    dim3 g2((N_NODES + 127) / 128, 1);
    tf32_dual_gemm<<<g2, 256>>>(out_h1r, W_self2, W_neigh2, b2, hs2, t2, N_NODES, 64);

    // launch 8: layer-2 gather + combine
    gather_combine2<<<gblocks, 256>>>(hs2, t2, out_h2a, out_h2b);
}

// round 13
// speedup vs baseline: 1.5201x; 1.5201x over previous
#include <cuda_runtime.h>
#include <cstddef>
#include <cstdint>

#define N_NODES 100000
#define N_EDGES 1600000
#define NB_SCAN 391            // ceil(100000 / 256)

// ---------------- scratch (static device arrays; no cudaMalloc) ------------
__device__ float g_t1[(size_t)N_NODES * 128];     // x @ W_neigh1
__device__ float g_hself1[(size_t)N_NODES * 128]; // x @ W_self1 + b1
__device__ float g_t2[(size_t)N_NODES * 64];      // h1_relu @ W_neigh2
__device__ float g_hself2[(size_t)N_NODES * 64];  // h1_relu @ W_self2 + b2
__device__ int   g_deg[N_NODES];                  // zero-init; re-zeroed by scatter
__device__ int   g_off[N_NODES + 1];
__device__ int   g_cur[N_NODES];
__device__ int   g_ssrc[N_EDGES];
__device__ int   g_bsum[512];
__device__ int   g_bpref[512];

// ---------------- CSR build (parallel two-level scan) -----------------------
__global__ void count_deg_kernel(const int* __restrict__ dst) {
    int e = blockIdx.x * blockDim.x + threadIdx.x;
    if (e < N_EDGES) atomicAdd(&g_deg[dst[e]], 1);
}

__global__ __launch_bounds__(256)
void block_sum_kernel() {
    __shared__ int sh[8];
    int i = blockIdx.x * 256 + threadIdx.x;
    int v = (i < N_NODES) ? g_deg[i] : 0;
    for (int o = 16; o > 0; o >>= 1) v += __shfl_down_sync(0xffffffffu, v, o);
    if ((threadIdx.x & 31) == 0) sh[threadIdx.x >> 5] = v;
    __syncthreads();
    if (threadIdx.x < 8) {
        int s = sh[threadIdx.x];
        for (int o = 4; o > 0; o >>= 1) s += __shfl_down_sync(0xffu, s, o);
        if (threadIdx.x == 0) g_bsum[blockIdx.x] = s;
    }
}

__global__ __launch_bounds__(512)
void block_scan_kernel() {
    __shared__ int sh[512];
    int t = threadIdx.x;
    int v = (t < NB_SCAN) ? g_bsum[t] : 0;
    sh[t] = v;
    __syncthreads();
    for (int o = 1; o < 512; o <<= 1) {
        int u = (t >= o) ? sh[t - o] : 0;
        __syncthreads();
        sh[t] += u;
        __syncthreads();
    }
    if (t < NB_SCAN) g_bpref[t] = sh[t] - v;
}

__global__ __launch_bounds__(256)
void scatter_offsets_kernel() {
    __shared__ int sh[256];
    int t = threadIdx.x;
    int i = blockIdx.x * 256 + t;
    int v = (i < N_NODES) ? g_deg[i] : 0;
    sh[t] = v;
    __syncthreads();
    for (int o = 1; o < 256; o <<= 1) {
        int u = (t >= o) ? sh[t - o] : 0;
        __syncthreads();
        sh[t] += u;
        __syncthreads();
    }
    if (i < N_NODES) {
        int off = g_bpref[blockIdx.x] + sh[t] - v;
        g_off[i] = off;
        g_cur[i] = off;
        g_deg[i] = 0;
    }
    if (blockIdx.x == 0 && t == 0) g_off[N_NODES] = N_EDGES;
}

__global__ void fill_csr_kernel(const int* __restrict__ src,
                                const int* __restrict__ dst) {
    int e = blockIdx.x * blockDim.x + threadIdx.x;
    if (e < N_EDGES) {
        int p = atomicAdd(&g_cur[dst[e]], 1);
        g_ssrc[p] = src[e];
    }
}

// ---------------- 3xBF16-split tensor-core dual-output GEMM ----------------
// a = ah + al (bf16 planes); D += ah*bh + ah*bl + al*bh  (err ~1e-4)
// BM=128 BN=128 BK=16; 8 warps as 4(M)x2(N); warp tile 32x64; m16n8k16.

__device__ __forceinline__ uint32_t pack_bf16x2(float lo_val, float hi_val) {
    uint32_t r;
    asm("cvt.rn.satfinite.bf16x2.f32 %0, %1, %2;" : "=r"(r) : "f"(hi_val), "f"(lo_val));
    return r;
}
__device__ __forceinline__ float unpk_lo(uint32_t p) { return __uint_as_float(p << 16); }
__device__ __forceinline__ float unpk_hi(uint32_t p) { return __uint_as_float(p & 0xffff0000u); }

__device__ __forceinline__ void mma_bf16(float* c,
                                         uint32_t a0, uint32_t a1, uint32_t a2, uint32_t a3,
                                         uint32_t b0, uint32_t b1) {
    asm volatile(
        "mma.sync.aligned.m16n8k16.row.col.f32.bf16.bf16.f32 "
        "{%0,%1,%2,%3}, {%4,%5,%6,%7}, {%8,%9}, {%0,%1,%2,%3};\n"
        : "+f"(c[0]), "+f"(c[1]), "+f"(c[2]), "+f"(c[3])
        : "r"(a0), "r"(a1), "r"(a2), "r"(a3), "r"(b0), "r"(b1));
}

#define A_PITCH 12            // uint2 per A row (8 data + 4 pad)
#define B_PITCH 132           // uint2 per B kc-row (128 data + 4 pad)

__global__ __launch_bounds__(256, 2)
void bf16_dual_gemm(const float* __restrict__ A,
                    const float* __restrict__ B0,
                    const float* __restrict__ B1,
                    const float* __restrict__ bias,
                    float* __restrict__ out0,
                    float* __restrict__ out1,
                    int M, int n0) {
    constexpr int BM = 128, BK = 16, K = 128;
    // As[m][kc]: kc = k/2 within tile; .x = hi bf16x2 pair, .y = lo pair
    __shared__ uint2 As[BM * A_PITCH];
    // Bs[kc][n]
    __shared__ uint2 Bs[(BK / 2) * B_PITCH];

    const int tid  = threadIdx.x;
    const int lane = tid & 31;
    const int warp = tid >> 5;
    const int g    = lane >> 2;          // 0..7
    const int tg   = lane & 3;           // 0..3
    const int warpM = (warp >> 1) * 32;  // 0,32,64,96
    const int warpN = (warp & 1) * 64;   // 0,64
    const int brow = blockIdx.x * BM;
    const int bcol = blockIdx.y * 128;

    // A staging mapping: row = tid>>1 (128 rows), k-half = (tid&1)*8
    const int aRow = tid >> 1;
    const int aKb  = (tid & 1) * 8;      // k offset within tile
    const int aKc  = (tid & 1) * 4;      // kc offset
    const bool aOK = (brow + aRow) < M;
    const float* aBase = A + (size_t)(brow + aRow) * K + aKb;

    // B staging mapping: kc-row r = tid>>5 (8), col lane nloc = tid&31; 4 cols/thread
    const int bR   = tid >> 5;
    const int bNl  = tid & 31;
    const float* bptr[4];
#pragma unroll
    for (int j = 0; j < 4; j++) {
        int gc = bcol + bNl + 32 * j;
        bptr[j] = (gc < n0) ? (B0 + gc) : (B1 + (gc - n0));
    }

    float acc[2][8][4];
#pragma unroll
    for (int mt = 0; mt < 2; mt++)
#pragma unroll
        for (int nt = 0; nt < 8; nt++)
#pragma unroll
            for (int q = 0; q < 4; q++) acc[mt][nt][q] = 0.f;

    for (int k0 = 0; k0 < K; k0 += BK) {
        // ---- stage A: 8 consecutive k per thread -> 4 packed kc entries ----
        {
            float4 v0 = make_float4(0.f, 0.f, 0.f, 0.f), v1 = v0;
            if (aOK) {
                v0 = *reinterpret_cast<const float4*>(aBase + k0);
                v1 = *reinterpret_cast<const float4*>(aBase + k0 + 4);
            }
            float fe[4] = {v0.x, v0.z, v1.x, v1.z};
            float fo[4] = {v0.y, v0.w, v1.y, v1.w};
#pragma unroll
            for (int j = 0; j < 4; j++) {
                uint32_t hp = pack_bf16x2(fe[j], fo[j]);
                float le = fe[j] - unpk_lo(hp);
                float lo = fo[j] - unpk_hi(hp);
                uint32_t lp = pack_bf16x2(le, lo);
                As[aRow * A_PITCH + aKc + j] = make_uint2(hp, lp);
            }
        }
        // ---- stage B: kc-row bR, 4 scattered n columns ----
        {
            size_t rowOff = (size_t)(k0 + 2 * bR) * n0;
#pragma unroll
            for (int j = 0; j < 4; j++) {
                float fe = bptr[j][rowOff];
                float fo = bptr[j][rowOff + n0];
                uint32_t hp = pack_bf16x2(fe, fo);
                float le = fe - unpk_lo(hp);
                float lo = fo - unpk_hi(hp);
                uint32_t lp = pack_bf16x2(le, lo);
                Bs[bR * B_PITCH + bNl + 32 * j] = make_uint2(hp, lp);
            }
        }
        __syncthreads();

        // ---- compute: one m16n8k16 k-step ----
        uint2 af[2][4];
#pragma unroll
        for (int mt = 0; mt < 2; mt++) {
            int m = warpM + mt * 16 + g;
            af[mt][0] = As[m * A_PITCH + tg];
            af[mt][1] = As[(m + 8) * A_PITCH + tg];
            af[mt][2] = As[m * A_PITCH + tg + 4];
            af[mt][3] = As[(m + 8) * A_PITCH + tg + 4];
        }
#pragma unroll
        for (int nt = 0; nt < 8; nt++) {
            int n = warpN + nt * 8 + g;
            uint2 b0 = Bs[tg * B_PITCH + n];
            uint2 b1 = Bs[(tg + 4) * B_PITCH + n];
#pragma unroll
            for (int mt = 0; mt < 2; mt++) {
                mma_bf16(acc[mt][nt], af[mt][0].x, af[mt][1].x, af[mt][2].x, af[mt][3].x,
                         b0.x, b1.x);                              // hi*hi
                mma_bf16(acc[mt][nt], af[mt][0].x, af[mt][1].x, af[mt][2].x, af[mt][3].x,
                         b0.y, b1.y);                              // hi*lo
                mma_bf16(acc[mt][nt], af[mt][0].y, af[mt][1].y, af[mt][2].y, af[mt][3].y,
                         b0.x, b1.x);                              // lo*hi
            }
        }
        __syncthreads();
    }

    // ---- epilogue (same fragment layout as m16n8 tf32) ----
#pragma unroll
    for (int mt = 0; mt < 2; mt++) {
#pragma unroll
        for (int nt = 0; nt < 8; nt++) {
            int gcol = bcol + warpN + nt * 8 + 2 * tg;
            int r0 = brow + warpM + mt * 16 + g;
            int r1 = r0 + 8;
            if (gcol < n0) {
                float bb0 = bias ? bias[gcol] : 0.f;
                float bb1 = bias ? bias[gcol + 1] : 0.f;
                if (r0 < M)
                    *reinterpret_cast<float2*>(out0 + (size_t)r0 * n0 + gcol) =
                        make_float2(acc[mt][nt][0] + bb0, acc[mt][nt][1] + bb1);
                if (r1 < M)
                    *reinterpret_cast<float2*>(out0 + (size_t)r1 * n0 + gcol) =
                        make_float2(acc[mt][nt][2] + bb0, acc[mt][nt][3] + bb1);
            } else {
                int cc = gcol - n0;
                if (r0 < M)
                    *reinterpret_cast<float2*>(out1 + (size_t)r0 * n0 + cc) =
                        make_float2(acc[mt][nt][0], acc[mt][nt][1]);
                if (r1 < M)
                    *reinterpret_cast<float2*>(out1 + (size_t)r1 * n0 + cc) =
                        make_float2(acc[mt][nt][2], acc[mt][nt][3]);
            }
        }
    }
}

// ---------------- layer-1 gather+combine: warp per dst node (D=128) --------
__global__ __launch_bounds__(256)
void gather_combine1(const float* __restrict__ hself,
                     const float* __restrict__ t,
                     float* __restrict__ out_h1,
                     float* __restrict__ out_h1r) {
    int warp = (blockIdx.x * blockDim.x + threadIdx.x) >> 5;
    int lane = threadIdx.x & 31;
    if (warp >= N_NODES) return;
    const int n   = warp;
    const int beg = g_off[n];
    const int end = g_off[n + 1];
    const int lo4 = lane * 4;

    float4 acc = make_float4(0.f, 0.f, 0.f, 0.f);
    int e = beg;
    for (; e + 3 < end; e += 4) {
        int s0 = g_ssrc[e];
        int s1 = g_ssrc[e + 1];
        int s2 = g_ssrc[e + 2];
        int s3 = g_ssrc[e + 3];
        float4 v0 = *reinterpret_cast<const float4*>(t + (size_t)s0 * 128 + lo4);
        float4 v1 = *reinterpret_cast<const float4*>(t + (size_t)s1 * 128 + lo4);
        float4 v2 = *reinterpret_cast<const float4*>(t + (size_t)s2 * 128 + lo4);
        float4 v3 = *reinterpret_cast<const float4*>(t + (size_t)s3 * 128 + lo4);
        acc.x += (v0.x + v1.x) + (v2.x + v3.x);
        acc.y += (v0.y + v1.y) + (v2.y + v3.y);
        acc.z += (v0.z + v1.z) + (v2.z + v3.z);
        acc.w += (v0.w + v1.w) + (v2.w + v3.w);
    }
    for (; e < end; e++) {
        int s0 = g_ssrc[e];
        float4 v0 = *reinterpret_cast<const float4*>(t + (size_t)s0 * 128 + lo4);
        acc.x += v0.x; acc.y += v0.y; acc.z += v0.z; acc.w += v0.w;
    }
    float inv = 1.0f / fmaxf((float)(end - beg), 1.0f);
    float4 hs = *reinterpret_cast<const float4*>(hself + (size_t)n * 128 + lo4);
    float4 h1;
    h1.x = hs.x + acc.x * inv;
    h1.y = hs.y + acc.y * inv;
    h1.z = hs.z + acc.z * inv;
    h1.w = hs.w + acc.w * inv;
    *reinterpret_cast<float4*>(out_h1 + (size_t)n * 128 + lo4) = h1;
    float4 r;
    r.x = fmaxf(h1.x, 0.f); r.y = fmaxf(h1.y, 0.f);
    r.z = fmaxf(h1.z, 0.f); r.w = fmaxf(h1.w, 0.f);
    *reinterpret_cast<float4*>(out_h1r + (size_t)n * 128 + lo4) = r;
}

// ---------------- layer-2 gather+combine: warp per dst node (D=64) ---------
__global__ __launch_bounds__(256)
void gather_combine2(const float* __restrict__ hself,
                     const float* __restrict__ t,
                     float* __restrict__ out_a,
                     float* __restrict__ out_b) {
    int warp = (blockIdx.x * blockDim.x + threadIdx.x) >> 5;
    int lane = threadIdx.x & 31;
    if (warp >= N_NODES) return;
    const int n   = warp;
    const int beg = g_off[n];
    const int end = g_off[n + 1];
    const int lo2 = lane * 2;

    float2 acc = make_float2(0.f, 0.f);
    int e = beg;
    for (; e + 3 < end; e += 4) {
        int s0 = g_ssrc[e];
        int s1 = g_ssrc[e + 1];
        int s2 = g_ssrc[e + 2];
        int s3 = g_ssrc[e + 3];
        float2 v0 = *reinterpret_cast<const float2*>(t + (size_t)s0 * 64 + lo2);
        float2 v1 = *reinterpret_cast<const float2*>(t + (size_t)s1 * 64 + lo2);
        float2 v2 = *reinterpret_cast<const float2*>(t + (size_t)s2 * 64 + lo2);
        float2 v3 = *reinterpret_cast<const float2*>(t + (size_t)s3 * 64 + lo2);
        acc.x += (v0.x + v1.x) + (v2.x + v3.x);
        acc.y += (v0.y + v1.y) + (v2.y + v3.y);
    }
    for (; e < end; e++) {
        int s0 = g_ssrc[e];
        float2 v0 = *reinterpret_cast<const float2*>(t + (size_t)s0 * 64 + lo2);
        acc.x += v0.x; acc.y += v0.y;
    }
    float inv = 1.0f / fmaxf((float)(end - beg), 1.0f);
    float2 hs = *reinterpret_cast<const float2*>(hself + (size_t)n * 64 + lo2);
    float2 h2 = make_float2(hs.x + acc.x * inv, hs.y + acc.y * inv);
    *reinterpret_cast<float2*>(out_a + (size_t)n * 64 + lo2) = h2;
    *reinterpret_cast<float2*>(out_b + (size_t)n * 64 + lo2) = h2;
}

// ---------------- launch ---------------------------------------------------
extern "C" void kernel_launch(void* const* d_in, const int* in_sizes, int n_in,
                              void* d_out, int out_size) {
    const float* x        = (const float*)d_in[0];
    const float* W_self1  = (const float*)d_in[1];
    const float* W_neigh1 = (const float*)d_in[2];
    const float* b1       = (const float*)d_in[3];
    const float* W_self2  = (const float*)d_in[4];
    const float* W_neigh2 = (const float*)d_in[5];
    const float* b2       = (const float*)d_in[6];
    const int*   src      = (const int*)d_in[7];
    const int*   dst      = (const int*)d_in[8];

    float* out = (float*)d_out;
    float* out_h2a = out;                                      // 100000*64
    float* out_h1  = out + (size_t)N_NODES * 64;               // 100000*128
    float* out_h1r = out + (size_t)N_NODES * (64 + 128);       // 100000*128
    float* out_h2b = out + (size_t)N_NODES * (64 + 128 + 128); // 100000*64

    float* t1 = nullptr, *hs1 = nullptr, *t2 = nullptr, *hs2 = nullptr;
    cudaGetSymbolAddress((void**)&t1,  g_t1);
    cudaGetSymbolAddress((void**)&hs1, g_hself1);
    cudaGetSymbolAddress((void**)&t2,  g_t2);
    cudaGetSymbolAddress((void**)&hs2, g_hself2);

    // launches 0..2: CSR count + scan levels
    count_deg_kernel<<<(N_EDGES + 255) / 256, 256>>>(dst);
    block_sum_kernel<<<NB_SCAN, 256>>>();
    block_scan_kernel<<<1, 512>>>();

    // launch 3 (ncu capture slot): layer-1 GEMM (independent of CSR)
    dim3 g1((N_NODES + 127) / 128, 2);
    bf16_dual_gemm<<<g1, 256>>>(x, W_self1, W_neigh1, b1, hs1, t1, N_NODES, 128);

    // launches 4..5: finish CSR
    scatter_offsets_kernel<<<NB_SCAN, 256>>>();
    fill_csr_kernel<<<(N_EDGES + 255) / 256, 256>>>(src, dst);

    // launch 6: layer-1 gather + combine + relu
    int gblocks = (N_NODES * 32 + 255) / 256;  // one warp per node
    gather_combine1<<<gblocks, 256>>>(hs1, t1, out_h1, out_h1r);

    // launch 7: layer-2 GEMM on h1_relu
    dim3 g2((N_NODES + 127) / 128, 1);
    bf16_dual_gemm<<<g2, 256>>>(out_h1r, W_self2, W_neigh2, b2, hs2, t2, N_NODES, 64);

    // launch 8: layer-2 gather + combine
    gather_combine2<<<gblocks, 256>>>(hs2, t2, out_h2a, out_h2b);
}

// round 14
// speedup vs baseline: 1.6089x; 1.0584x over previous
#include <cuda_runtime.h>
#include <cstddef>
#include <cstdint>

#define N_NODES 100000
#define N_EDGES 1600000
#define NB_SCAN 391            // ceil(100000 / 256)

// ---------------- scratch (static device arrays; no cudaMalloc) ------------
__device__ float g_t1[(size_t)N_NODES * 128];     // x @ W_neigh1
__device__ float g_hself1[(size_t)N_NODES * 128]; // x @ W_self1 + b1
__device__ float g_t2[(size_t)N_NODES * 64];      // h1_relu @ W_neigh2
__device__ float g_hself2[(size_t)N_NODES * 64];  // h1_relu @ W_self2 + b2
__device__ int   g_deg[N_NODES];                  // zero-init; re-zeroed by scatter
__device__ int   g_off[N_NODES + 1];
__device__ int   g_cur[N_NODES];
__device__ int   g_ssrc[N_EDGES];
__device__ int   g_bsum[512];
__device__ int   g_bpref[512];

// ---------------- CSR build (parallel two-level scan) -----------------------
__global__ void count_deg_kernel(const int* __restrict__ dst) {
    int e = blockIdx.x * blockDim.x + threadIdx.x;
    if (e < N_EDGES) atomicAdd(&g_deg[dst[e]], 1);
}

__global__ __launch_bounds__(256)
void block_sum_kernel() {
    __shared__ int sh[8];
    int i = blockIdx.x * 256 + threadIdx.x;
    int v = (i < N_NODES) ? g_deg[i] : 0;
    for (int o = 16; o > 0; o >>= 1) v += __shfl_down_sync(0xffffffffu, v, o);
    if ((threadIdx.x & 31) == 0) sh[threadIdx.x >> 5] = v;
    __syncthreads();
    if (threadIdx.x < 8) {
        int s = sh[threadIdx.x];
        for (int o = 4; o > 0; o >>= 1) s += __shfl_down_sync(0xffu, s, o);
        if (threadIdx.x == 0) g_bsum[blockIdx.x] = s;
    }
}

__global__ __launch_bounds__(512)
void block_scan_kernel() {
    __shared__ int sh[512];
    int t = threadIdx.x;
    int v = (t < NB_SCAN) ? g_bsum[t] : 0;
    sh[t] = v;
    __syncthreads();
    for (int o = 1; o < 512; o <<= 1) {
        int u = (t >= o) ? sh[t - o] : 0;
        __syncthreads();
        sh[t] += u;
        __syncthreads();
    }
    if (t < NB_SCAN) g_bpref[t] = sh[t] - v;
}

__global__ __launch_bounds__(256)
void scatter_offsets_kernel() {
    __shared__ int sh[256];
    int t = threadIdx.x;
    int i = blockIdx.x * 256 + t;
    int v = (i < N_NODES) ? g_deg[i] : 0;
    sh[t] = v;
    __syncthreads();
    for (int o = 1; o < 256; o <<= 1) {
        int u = (t >= o) ? sh[t - o] : 0;
        __syncthreads();
        sh[t] += u;
        __syncthreads();
    }
    if (i < N_NODES) {
        int off = g_bpref[blockIdx.x] + sh[t] - v;
        g_off[i] = off;
        g_cur[i] = off;
        g_deg[i] = 0;
    }
    if (blockIdx.x == 0 && t == 0) g_off[N_NODES] = N_EDGES;
}

__global__ void fill_csr_kernel(const int* __restrict__ src,
                                const int* __restrict__ dst) {
    int e = blockIdx.x * blockDim.x + threadIdx.x;
    if (e < N_EDGES) {
        int p = atomicAdd(&g_cur[dst[e]], 1);
        g_ssrc[p] = src[e];
    }
}

// ---------------- 3xBF16-split tensor-core dual-output GEMM ----------------
__device__ __forceinline__ uint32_t pack_bf16x2(float lo_val, float hi_val) {
    uint32_t r;
    asm("cvt.rn.satfinite.bf16x2.f32 %0, %1, %2;" : "=r"(r) : "f"(hi_val), "f"(lo_val));
    return r;
}
__device__ __forceinline__ float unpk_lo(uint32_t p) { return __uint_as_float(p << 16); }
__device__ __forceinline__ float unpk_hi(uint32_t p) { return __uint_as_float(p & 0xffff0000u); }

__device__ __forceinline__ void mma_bf16(float* c,
                                         uint32_t a0, uint32_t a1, uint32_t a2, uint32_t a3,
                                         uint32_t b0, uint32_t b1) {
    asm volatile(
        "mma.sync.aligned.m16n8k16.row.col.f32.bf16.bf16.f32 "
        "{%0,%1,%2,%3}, {%4,%5,%6,%7}, {%8,%9}, {%0,%1,%2,%3};\n"
        : "+f"(c[0]), "+f"(c[1]), "+f"(c[2]), "+f"(c[3])
        : "r"(a0), "r"(a1), "r"(a2), "r"(a3), "r"(b0), "r"(b1));
}

#define A_PITCH 12            // uint2 per A row (8 data + 4 pad)
#define B_PITCH 132           // uint2 per B kc-row (128 data + 4 pad)

__global__ __launch_bounds__(256, 2)
void bf16_dual_gemm(const float* __restrict__ A,
                    const float* __restrict__ B0,
                    const float* __restrict__ B1,
                    const float* __restrict__ bias,
                    float* __restrict__ out0,
                    float* __restrict__ out1,
                    int M, int n0) {
    constexpr int BM = 128, BK = 16, K = 128;
    __shared__ uint2 As[BM * A_PITCH];
    __shared__ uint2 Bs[(BK / 2) * B_PITCH];

    const int tid  = threadIdx.x;
    const int lane = tid & 31;
    const int warp = tid >> 5;
    const int g    = lane >> 2;
    const int tg   = lane & 3;
    const int warpM = (warp >> 1) * 32;
    const int warpN = (warp & 1) * 64;
    const int brow = blockIdx.x * BM;
    const int bcol = blockIdx.y * 128;

    const int aRow = tid >> 1;
    const int aKb  = (tid & 1) * 8;
    const int aKc  = (tid & 1) * 4;
    const bool aOK = (brow + aRow) < M;
    const float* aBase = A + (size_t)(brow + aRow) * K + aKb;

    const int bR   = tid >> 5;
    const int bNl  = tid & 31;
    const float* bptr[4];
#pragma unroll
    for (int j = 0; j < 4; j++) {
        int gc = bcol + bNl + 32 * j;
        bptr[j] = (gc < n0) ? (B0 + gc) : (B1 + (gc - n0));
    }

    float acc[2][8][4];
#pragma unroll
    for (int mt = 0; mt < 2; mt++)
#pragma unroll
        for (int nt = 0; nt < 8; nt++)
#pragma unroll
            for (int q = 0; q < 4; q++) acc[mt][nt][q] = 0.f;

    for (int k0 = 0; k0 < K; k0 += BK) {
        {
            float4 v0 = make_float4(0.f, 0.f, 0.f, 0.f), v1 = v0;
            if (aOK) {
                v0 = *reinterpret_cast<const float4*>(aBase + k0);
                v1 = *reinterpret_cast<const float4*>(aBase + k0 + 4);
            }
            float fe[4] = {v0.x, v0.z, v1.x, v1.z};
            float fo[4] = {v0.y, v0.w, v1.y, v1.w};
#pragma unroll
            for (int j = 0; j < 4; j++) {
                uint32_t hp = pack_bf16x2(fe[j], fo[j]);
                float le = fe[j] - unpk_lo(hp);
                float lo = fo[j] - unpk_hi(hp);
                uint32_t lp = pack_bf16x2(le, lo);
                As[aRow * A_PITCH + aKc + j] = make_uint2(hp, lp);
            }
        }
        {
            size_t rowOff = (size_t)(k0 + 2 * bR) * n0;
#pragma unroll
            for (int j = 0; j < 4; j++) {
                float fe = bptr[j][rowOff];
                float fo = bptr[j][rowOff + n0];
                uint32_t hp = pack_bf16x2(fe, fo);
                float le = fe - unpk_lo(hp);
                float lo = fo - unpk_hi(hp);
                uint32_t lp = pack_bf16x2(le, lo);
                Bs[bR * B_PITCH + bNl + 32 * j] = make_uint2(hp, lp);
            }
        }
        __syncthreads();

        uint2 af[2][4];
#pragma unroll
        for (int mt = 0; mt < 2; mt++) {
            int m = warpM + mt * 16 + g;
            af[mt][0] = As[m * A_PITCH + tg];
            af[mt][1] = As[(m + 8) * A_PITCH + tg];
            af[mt][2] = As[m * A_PITCH + tg + 4];
            af[mt][3] = As[(m + 8) * A_PITCH + tg + 4];
        }
#pragma unroll
        for (int nt = 0; nt < 8; nt++) {
            int n = warpN + nt * 8 + g;
            uint2 b0 = Bs[tg * B_PITCH + n];
            uint2 b1 = Bs[(tg + 4) * B_PITCH + n];
#pragma unroll
            for (int mt = 0; mt < 2; mt++) {
                mma_bf16(acc[mt][nt], af[mt][0].x, af[mt][1].x, af[mt][2].x, af[mt][3].x,
                         b0.x, b1.x);
                mma_bf16(acc[mt][nt], af[mt][0].x, af[mt][1].x, af[mt][2].x, af[mt][3].x,
                         b0.y, b1.y);
                mma_bf16(acc[mt][nt], af[mt][0].y, af[mt][1].y, af[mt][2].y, af[mt][3].y,
                         b0.x, b1.x);
            }
        }
        __syncthreads();
    }

#pragma unroll
    for (int mt = 0; mt < 2; mt++) {
#pragma unroll
        for (int nt = 0; nt < 8; nt++) {
            int gcol = bcol + warpN + nt * 8 + 2 * tg;
            int r0 = brow + warpM + mt * 16 + g;
            int r1 = r0 + 8;
            if (gcol < n0) {
                float bb0 = bias ? bias[gcol] : 0.f;
                float bb1 = bias ? bias[gcol + 1] : 0.f;
                if (r0 < M)
                    *reinterpret_cast<float2*>(out0 + (size_t)r0 * n0 + gcol) =
                        make_float2(acc[mt][nt][0] + bb0, acc[mt][nt][1] + bb1);
                if (r1 < M)
                    *reinterpret_cast<float2*>(out0 + (size_t)r1 * n0 + gcol) =
                        make_float2(acc[mt][nt][2] + bb0, acc[mt][nt][3] + bb1);
            } else {
                int cc = gcol - n0;
                if (r0 < M)
                    *reinterpret_cast<float2*>(out1 + (size_t)r0 * n0 + cc) =
                        make_float2(acc[mt][nt][0], acc[mt][nt][1]);
                if (r1 < M)
                    *reinterpret_cast<float2*>(out1 + (size_t)r1 * n0 + cc) =
                        make_float2(acc[mt][nt][2], acc[mt][nt][3]);
            }
        }
    }
}

// ---------------- layer-1 gather+combine: warp per dst node (D=128) --------
__global__ __launch_bounds__(256)
void gather_combine1(const float* __restrict__ hself,
                     const float* __restrict__ t,
                     float* __restrict__ out_h1,
                     float* __restrict__ out_h1r) {
    int warp = (blockIdx.x * blockDim.x + threadIdx.x) >> 5;
    int lane = threadIdx.x & 31;
    if (warp >= N_NODES) return;
    const int n   = warp;
    const int beg = g_off[n];
    const int end = g_off[n + 1];
    const int lo4 = lane * 4;

    float4 acc = make_float4(0.f, 0.f, 0.f, 0.f);
    int e = beg;
    for (; e + 3 < end; e += 4) {
        int s0 = g_ssrc[e];
        int s1 = g_ssrc[e + 1];
        int s2 = g_ssrc[e + 2];
        int s3 = g_ssrc[e + 3];
        float4 v0 = *reinterpret_cast<const float4*>(t + (size_t)s0 * 128 + lo4);
        float4 v1 = *reinterpret_cast<const float4*>(t + (size_t)s1 * 128 + lo4);
        float4 v2 = *reinterpret_cast<const float4*>(t + (size_t)s2 * 128 + lo4);
        float4 v3 = *reinterpret_cast<const float4*>(t + (size_t)s3 * 128 + lo4);
        acc.x += (v0.x + v1.x) + (v2.x + v3.x);
        acc.y += (v0.y + v1.y) + (v2.y + v3.y);
        acc.z += (v0.z + v1.z) + (v2.z + v3.z);
        acc.w += (v0.w + v1.w) + (v2.w + v3.w);
    }
    for (; e < end; e++) {
        int s0 = g_ssrc[e];
        float4 v0 = *reinterpret_cast<const float4*>(t + (size_t)s0 * 128 + lo4);
        acc.x += v0.x; acc.y += v0.y; acc.z += v0.z; acc.w += v0.w;
    }
    float inv = 1.0f / fmaxf((float)(end - beg), 1.0f);
    float4 hs = *reinterpret_cast<const float4*>(hself + (size_t)n * 128 + lo4);
    float4 h1;
    h1.x = hs.x + acc.x * inv;
    h1.y = hs.y + acc.y * inv;
    h1.z = hs.z + acc.z * inv;
    h1.w = hs.w + acc.w * inv;
    *reinterpret_cast<float4*>(out_h1 + (size_t)n * 128 + lo4) = h1;
    float4 r;
    r.x = fmaxf(h1.x, 0.f); r.y = fmaxf(h1.y, 0.f);
    r.z = fmaxf(h1.z, 0.f); r.w = fmaxf(h1.w, 0.f);
    *reinterpret_cast<float4*>(out_h1r + (size_t)n * 128 + lo4) = r;
}

// ---------------- layer-2 gather+combine: warp per dst node (D=64) ---------
__global__ __launch_bounds__(256)
void gather_combine2(const float* __restrict__ hself,
                     const float* __restrict__ t,
                     float* __restrict__ out_a,
                     float* __restrict__ out_b) {
    int warp = (blockIdx.x * blockDim.x + threadIdx.x) >> 5;
    int lane = threadIdx.x & 31;
    if (warp >= N_NODES) return;
    const int n   = warp;
    const int beg = g_off[n];
    const int end = g_off[n + 1];
    const int lo2 = lane * 2;

    float2 acc = make_float2(0.f, 0.f);
    int e = beg;
    for (; e + 3 < end; e += 4) {
        int s0 = g_ssrc[e];
        int s1 = g_ssrc[e + 1];
        int s2 = g_ssrc[e + 2];
        int s3 = g_ssrc[e + 3];
        float2 v0 = *reinterpret_cast<const float2*>(t + (size_t)s0 * 64 + lo2);
        float2 v1 = *reinterpret_cast<const float2*>(t + (size_t)s1 * 64 + lo2);
        float2 v2 = *reinterpret_cast<const float2*>(t + (size_t)s2 * 64 + lo2);
        float2 v3 = *reinterpret_cast<const float2*>(t + (size_t)s3 * 64 + lo2);
        acc.x += (v0.x + v1.x) + (v2.x + v3.x);
        acc.y += (v0.y + v1.y) + (v2.y + v3.y);
    }
    for (; e < end; e++) {
        int s0 = g_ssrc[e];
        float2 v0 = *reinterpret_cast<const float2*>(t + (size_t)s0 * 64 + lo2);
        acc.x += v0.x; acc.y += v0.y;
    }
    float inv = 1.0f / fmaxf((float)(end - beg), 1.0f);
    float2 hs = *reinterpret_cast<const float2*>(hself + (size_t)n * 64 + lo2);
    float2 h2 = make_float2(hs.x + acc.x * inv, hs.y + acc.y * inv);
    *reinterpret_cast<float2*>(out_a + (size_t)n * 64 + lo2) = h2;
    *reinterpret_cast<float2*>(out_b + (size_t)n * 64 + lo2) = h2;
}

// ---------------- launch ---------------------------------------------------
extern "C" void kernel_launch(void* const* d_in, const int* in_sizes, int n_in,
                              void* d_out, int out_size) {
    const float* x        = (const float*)d_in[0];
    const float* W_self1  = (const float*)d_in[1];
    const float* W_neigh1 = (const float*)d_in[2];
    const float* b1       = (const float*)d_in[3];
    const float* W_self2  = (const float*)d_in[4];
    const float* W_neigh2 = (const float*)d_in[5];
    const float* b2       = (const float*)d_in[6];
    const int*   src      = (const int*)d_in[7];
    const int*   dst      = (const int*)d_in[8];

    float* out = (float*)d_out;
    float* out_h2a = out;                                      // 100000*64
    float* out_h1  = out + (size_t)N_NODES * 64;               // 100000*128
    float* out_h1r = out + (size_t)N_NODES * (64 + 128);       // 100000*128
    float* out_h2b = out + (size_t)N_NODES * (64 + 128 + 128); // 100000*64

    float* t1 = nullptr, *hs1 = nullptr, *t2 = nullptr, *hs2 = nullptr;
    cudaGetSymbolAddress((void**)&t1,  g_t1);
    cudaGetSymbolAddress((void**)&hs1, g_hself1);
    cudaGetSymbolAddress((void**)&t2,  g_t2);
    cudaGetSymbolAddress((void**)&hs2, g_hself2);

    // Side stream for the CSR chain (independent of GEMM1). Created fresh
    // each call (kernel_launch runs only for correctness + capture, not the
    // timed replays). Fork/join via events is the documented multi-stream
    // graph-capture pattern.
    cudaStream_t s2;
    cudaStreamCreate(&s2);
    cudaEvent_t eFork, eJoin;
    cudaEventCreateWithFlags(&eFork, cudaEventDisableTiming);
    cudaEventCreateWithFlags(&eJoin, cudaEventDisableTiming);

    cudaEventRecord(eFork, 0);           // fork from main (capturing) stream
    cudaStreamWaitEvent(s2, eFork, 0);   // s2 enters the capture graph

    // CSR chain on s2 (launches 1,2, then 4,5 in submission order)
    count_deg_kernel<<<(N_EDGES + 255) / 256, 256, 0, s2>>>(dst);
    block_sum_kernel<<<NB_SCAN, 256, 0, s2>>>();
    block_scan_kernel<<<1, 512, 0, s2>>>();

    // launch slot 3 (ncu capture): layer-1 GEMM on main stream, overlapped
    dim3 g1((N_NODES + 127) / 128, 2);
    bf16_dual_gemm<<<g1, 256>>>(x, W_self1, W_neigh1, b1, hs1, t1, N_NODES, 128);

    scatter_offsets_kernel<<<NB_SCAN, 256, 0, s2>>>();
    fill_csr_kernel<<<(N_EDGES + 255) / 256, 256, 0, s2>>>(src, dst);

    cudaEventRecord(eJoin, s2);          // join CSR chain back into main
    cudaStreamWaitEvent(0, eJoin, 0);

    // gather1 needs GEMM1 (main-stream order) + CSR (join event)
    int gblocks = (N_NODES * 32 + 255) / 256;  // one warp per node
    gather_combine1<<<gblocks, 256>>>(hs1, t1, out_h1, out_h1r);

    dim3 g2((N_NODES + 127) / 128, 1);
    bf16_dual_gemm<<<g2, 256>>>(out_h1r, W_self2, W_neigh2, b2, hs2, t2, N_NODES, 64);

    gather_combine2<<<gblocks, 256>>>(hs2, t2, out_h2a, out_h2b);
}